// round 1
// baseline (speedup 1.0000x reference)
#include <cuda_runtime.h>
#include <math.h>

#define B 64
#define S 64
#define L 64
#define H 1024
#define CDIM 2048
#define E 512
#define OC (H + E + CDIM)   // 3584
#define XK (E + CDIM)       // 2560
#define G3 (3 * H)          // 3072

// ---------------- scratch (device globals; no allocation allowed) ----------
__device__ float g_ctxproj[B * L * H];   // 16.8 MB
__device__ float g_h[B * H];
__device__ float g_q[B * H];
__device__ float g_score[B * L];
__device__ float g_gi[B * G3];
__device__ float g_gh[B * G3];

// ---------------- init: h <- hidden0, zero accumulators --------------------
__global__ void k_init(const float* __restrict__ h0) {
    int i = blockIdx.x * blockDim.x + threadIdx.x;
    if (i < B * H) { g_h[i] = h0[i]; g_q[i] = 0.f; }
    if (i < B * G3) { g_gi[i] = 0.f; g_gh[i] = 0.f; }
}

// ---------------- embedding gather into output rows ------------------------
// out row = b*S + s ; columns [H, H+E) = emb_t
__global__ void k_emb(const int* __restrict__ tgt,
                      const float* __restrict__ emb,
                      float* __restrict__ out) {
    int row = blockIdx.x;                       // b*S + s
    int tok = tgt[row];
    const float4* src = (const float4*)(emb + (size_t)tok * E);
    float4* dst = (float4*)(out + (size_t)row * OC + H);
    dst[threadIdx.x] = src[threadIdx.x];        // 128 threads * 4 floats = E
}

// ---------------- generic NT GEMM: C[M,N] (+)= A[M,K] * B[N,K]^T ------------
// Block tile 64(m) x 128(n), BK=16, 256 threads, 4x8 per-thread tile.
// grid.x = N/128, grid.y = M/64, grid.z = K / kc  (split-K, atomic accumulate)
template <bool ATOMIC>
__global__ void gemm_nt(const float* __restrict__ A, int lda,
                        const float* __restrict__ Bm, int ldb,
                        float* __restrict__ Cm, int ldc,
                        int kc) {
    const int BK = 16;
    __shared__ float As[BK][64 + 4];
    __shared__ float Bs[BK][128 + 4];

    const int tid = threadIdx.x;
    const int tx = tid & 15;        // n group (0..15)
    const int ty = tid >> 4;        // m group (0..15)
    const int m0 = blockIdx.y * 64;
    const int n0 = blockIdx.x * 128;
    const int k0 = blockIdx.z * kc;
    const int k1 = k0 + kc;

    // A load mapping: one float4 per thread
    const int arow = tid >> 2;      // 0..63
    const int akq  = tid & 3;       // 0..3  (k quad)
    // B load mapping: two float4 per thread
    const int bidx0 = tid * 2;
    const int bidx1 = tid * 2 + 1;
    const int brow0 = bidx0 >> 2, bkq0 = bidx0 & 3;
    const int brow1 = bidx1 >> 2, bkq1 = bidx1 & 3;

    float acc[4][8];
#pragma unroll
    for (int m = 0; m < 4; m++)
#pragma unroll
        for (int j = 0; j < 8; j++) acc[m][j] = 0.f;

    for (int kb = k0; kb < k1; kb += BK) {
        float4 av  = *(const float4*)(A  + (size_t)(m0 + arow)  * lda + kb + akq * 4);
        float4 bv0 = *(const float4*)(Bm + (size_t)(n0 + brow0) * ldb + kb + bkq0 * 4);
        float4 bv1 = *(const float4*)(Bm + (size_t)(n0 + brow1) * ldb + kb + bkq1 * 4);

        __syncthreads();
        As[akq * 4 + 0][arow] = av.x;
        As[akq * 4 + 1][arow] = av.y;
        As[akq * 4 + 2][arow] = av.z;
        As[akq * 4 + 3][arow] = av.w;
        Bs[bkq0 * 4 + 0][brow0] = bv0.x;
        Bs[bkq0 * 4 + 1][brow0] = bv0.y;
        Bs[bkq0 * 4 + 2][brow0] = bv0.z;
        Bs[bkq0 * 4 + 3][brow0] = bv0.w;
        Bs[bkq1 * 4 + 0][brow1] = bv1.x;
        Bs[bkq1 * 4 + 1][brow1] = bv1.y;
        Bs[bkq1 * 4 + 2][brow1] = bv1.z;
        Bs[bkq1 * 4 + 3][brow1] = bv1.w;
        __syncthreads();

#pragma unroll
        for (int kk = 0; kk < BK; kk++) {
            float4 a  = *(const float4*)(&As[kk][ty * 4]);
            float4 b0 = *(const float4*)(&Bs[kk][tx * 4]);
            float4 b1 = *(const float4*)(&Bs[kk][64 + tx * 4]);
            float am[4] = {a.x, a.y, a.z, a.w};
            float bn[8] = {b0.x, b0.y, b0.z, b0.w, b1.x, b1.y, b1.z, b1.w};
#pragma unroll
            for (int m = 0; m < 4; m++)
#pragma unroll
                for (int j = 0; j < 8; j++) acc[m][j] += am[m] * bn[j];
        }
    }

#pragma unroll
    for (int m = 0; m < 4; m++) {
        const int row = m0 + ty * 4 + m;
        if (ATOMIC) {
#pragma unroll
            for (int j = 0; j < 4; j++)
                atomicAdd(Cm + (size_t)row * ldc + n0 + tx * 4 + j, acc[m][j]);
#pragma unroll
            for (int j = 0; j < 4; j++)
                atomicAdd(Cm + (size_t)row * ldc + n0 + 64 + tx * 4 + j, acc[m][4 + j]);
        } else {
            float4 o0 = {acc[m][0], acc[m][1], acc[m][2], acc[m][3]};
            float4 o1 = {acc[m][4], acc[m][5], acc[m][6], acc[m][7]};
            *(float4*)(Cm + (size_t)row * ldc + n0 + tx * 4)      = o0;
            *(float4*)(Cm + (size_t)row * ldc + n0 + 64 + tx * 4) = o1;
        }
    }
}

// ---------------- attention score: tanh(ctx_proj + q + bq) . v -------------
// grid (L, B), 256 threads
__global__ void k_score(const float* __restrict__ v, const float* __restrict__ bq) {
    const int l = blockIdx.x, b = blockIdx.y;
    const float* cp = g_ctxproj + ((size_t)(b * L + l)) * H;
    const float* qb = g_q + b * H;
    const int tid = threadIdx.x;

    float s = 0.f;
    for (int h = tid; h < H; h += 256)
        s += tanhf(cp[h] + qb[h] + bq[h]) * v[h];

#pragma unroll
    for (int o = 16; o; o >>= 1) s += __shfl_xor_sync(0xffffffffu, s, o);
    __shared__ float red[8];
    if ((tid & 31) == 0) red[tid >> 5] = s;
    __syncthreads();
    if (tid == 0) {
        float t = 0.f;
#pragma unroll
        for (int w = 0; w < 8; w++) t += red[w];
        g_score[b * L + l] = t;
    }
}

// ---------------- softmax + ctx_t = attn @ ctx ; write out ctx columns -----
// grid (B), 256 threads
__global__ void k_ctx(const float* __restrict__ ctx, float* __restrict__ out, int t) {
    const int b = blockIdx.x;
    const int tid = threadIdx.x;
    __shared__ float attn[L];

    if (tid < L) attn[tid] = g_score[b * L + tid];
    __syncthreads();
    if (tid < 32) {
        float m0 = fmaxf(attn[tid], attn[tid + 32]);
#pragma unroll
        for (int o = 16; o; o >>= 1) m0 = fmaxf(m0, __shfl_xor_sync(0xffffffffu, m0, o));
        float e0 = expf(attn[tid] - m0);
        float e1 = expf(attn[tid + 32] - m0);
        float ss = e0 + e1;
#pragma unroll
        for (int o = 16; o; o >>= 1) ss += __shfl_xor_sync(0xffffffffu, ss, o);
        attn[tid] = e0 / ss;
        attn[tid + 32] = e1 / ss;
    }
    __syncthreads();

    const float4* cb4 = (const float4*)(ctx + (size_t)b * L * CDIM);
    float4* orow4 = (float4*)(out + ((size_t)(b * S + t)) * OC + H + E);
    for (int c4 = tid; c4 < CDIM / 4; c4 += 256) {
        float4 acc = {0.f, 0.f, 0.f, 0.f};
#pragma unroll 8
        for (int l = 0; l < L; l++) {
            float a = attn[l];
            float4 x = cb4[l * (CDIM / 4) + c4];
            acc.x += a * x.x; acc.y += a * x.y;
            acc.z += a * x.z; acc.w += a * x.w;
        }
        orow4[c4] = acc;
    }
}

// ---------------- GRU gates + h update + out h_prev + zero scratch ---------
// grid (B*H/256), 256 threads
__global__ void k_gate(const float* __restrict__ b_ih, const float* __restrict__ b_hh,
                       float* __restrict__ out, int t) {
    const int idx = blockIdx.x * 256 + threadIdx.x;   // b*H + i
    const int b = idx >> 10, i = idx & 1023;
    const int g = b * G3;

    float ir = g_gi[g + i]         + b_ih[i];
    float iz = g_gi[g + H + i]     + b_ih[H + i];
    float in_ = g_gi[g + 2 * H + i] + b_ih[2 * H + i];
    float hr = g_gh[g + i]         + b_hh[i];
    float hz = g_gh[g + H + i]     + b_hh[H + i];
    float hn = g_gh[g + 2 * H + i] + b_hh[2 * H + i];

    float r = 1.f / (1.f + expf(-(ir + hr)));
    float z = 1.f / (1.f + expf(-(iz + hz)));
    float n = tanhf(in_ + r * hn);
    float hold = g_h[idx];
    float hnew = (1.f - z) * n + z * hold;

    g_h[idx] = hnew;
    out[((size_t)(b * S + t)) * OC + i] = hold;

    // zero accumulators for next step
    g_q[idx] = 0.f;
    g_gi[g + i] = 0.f; g_gi[g + H + i] = 0.f; g_gi[g + 2 * H + i] = 0.f;
    g_gh[g + i] = 0.f; g_gh[g + H + i] = 0.f; g_gh[g + 2 * H + i] = 0.f;
}

// ---------------- final hidden state --------------------------------------
__global__ void k_hlast(float* __restrict__ out) {
    int i = blockIdx.x * 256 + threadIdx.x;
    out[(size_t)B * S * OC + i] = g_h[i];
}

// ---------------------------------------------------------------------------
extern "C" void kernel_launch(void* const* d_in, const int* in_sizes, int n_in,
                              void* d_out, int out_size) {
    const int*   tgt  = (const int*)d_in[0];
    const float* ctx  = (const float*)d_in[1];
    const float* h0   = (const float*)d_in[2];
    const float* emb  = (const float*)d_in[3];
    const float* Wc   = (const float*)d_in[4];
    const float* Wq   = (const float*)d_in[5];
    const float* bq   = (const float*)d_in[6];
    const float* v    = (const float*)d_in[7];
    const float* W_ih = (const float*)d_in[8];
    const float* W_hh = (const float*)d_in[9];
    const float* b_ih = (const float*)d_in[10];
    const float* b_hh = (const float*)d_in[11];
    float* out = (float*)d_out;

    float *p_cp, *p_h, *p_q, *p_gi, *p_gh;
    cudaGetSymbolAddress((void**)&p_cp, g_ctxproj);
    cudaGetSymbolAddress((void**)&p_h,  g_h);
    cudaGetSymbolAddress((void**)&p_q,  g_q);
    cudaGetSymbolAddress((void**)&p_gi, g_gi);
    cudaGetSymbolAddress((void**)&p_gh, g_gh);

    k_init<<<(B * G3 + 255) / 256, 256>>>(h0);
    k_emb<<<B * S, 128>>>(tgt, emb, out);

    // ctx_proj[B*L, H] = ctx[B*L, C] @ Wc[H, C]^T   (one-time, full-K)
    gemm_nt<false><<<dim3(H / 128, (B * L) / 64, 1), 256>>>(
        ctx, CDIM, Wc, CDIM, p_cp, H, CDIM);

    for (int t = 0; t < S; t++) {
        // q[64,H] += h @ Wq^T    (split-K 16 x kc=64)
        gemm_nt<true><<<dim3(H / 128, 1, 16), 256>>>(
            p_h, H, Wq, H, p_q, H, 64);
        // attention scores
        k_score<<<dim3(L, B), 256>>>(v, bq);
        // softmax + ctx_t -> out row cols [H+E, OC)
        k_ctx<<<B, 256>>>(ctx, out, t);
        // gi[64,3H] += x @ W_ih^T ; x = out row cols [H, OC)  (split-K 8 x kc=320)
        gemm_nt<true><<<dim3(G3 / 128, 1, 8), 256>>>(
            out + (size_t)t * OC + H, S * OC, W_ih, XK, p_gi, G3, 320);
        // gh[64,3H] += h @ W_hh^T   (split-K 8 x kc=128)
        gemm_nt<true><<<dim3(G3 / 128, 1, 8), 256>>>(
            p_h, H, W_hh, H, p_gh, G3, 128);
        // gates, h update, write h_prev to out, zero accumulators
        k_gate<<<(B * H) / 256, 256>>>(b_ih, b_hh, out, t);
    }

    if (out_size >= B * S * OC + B * H)
        k_hlast<<<(B * H) / 256, 256>>>(out);
}

// round 2
// speedup vs baseline: 2.0582x; 2.0582x over previous
#include <cuda_runtime.h>
#include <math.h>

#define B 64
#define S 64
#define L 64
#define H 1024
#define CDIM 2048
#define E 512
#define OC (H + E + CDIM)   // 3584
#define XK (E + CDIM)       // 2560
#define G3 (3 * H)          // 3072

// ---------------- scratch (device globals) ---------------------------------
__device__ float g_ctxproj[B * L * H];     // 16.8 MB
__device__ float g_giemb[B * S * G3];      // 50.3 MB : emb @ W_ih[:, :E]^T
__device__ float g_h[B * H];
__device__ float g_q[B * H];
__device__ float g_score[B * L];
__device__ float g_gi[B * G3];             // ctx-part of gi accumulator
__device__ float g_gh[B * G3];

// ---------------- FFMA-only fast tanh (no MUFU) -----------------------------
__device__ __forceinline__ float tanh_fast(float x) {
    float y = fminf(fmaxf(x * 2.885390081777927f, -28.f), 28.f);  // 2x*log2(e)
    float tt = y + 12582912.f;                 // round-to-nearest trick
    int   ik = __float_as_int(tt) - 0x4B400000;
    float f  = y - (tt - 12582912.f);          // frac in [-0.5, 0.5]
    float p  = 1.5403530393e-4f;               // 2^f Taylor deg-6
    p = fmaf(p, f, 1.3333558146e-3f);
    p = fmaf(p, f, 9.6181291076e-3f);
    p = fmaf(p, f, 5.5504108664e-2f);
    p = fmaf(p, f, 2.4022650696e-1f);
    p = fmaf(p, f, 6.9314718056e-1f);
    p = fmaf(p, f, 1.0f);
    float e = __int_as_float(__float_as_int(p) + (ik << 23));     // e^{2x}
    float d = e + 1.0f;
    float r = __int_as_float(0x7EF311C3 - __float_as_int(d));     // ~1/d
    r = r * (2.0f - d * r);
    r = r * (2.0f - d * r);
    r = r * (2.0f - d * r);
    return (e - 1.0f) * r;                     // (e^{2x}-1)/(e^{2x}+1)
}

// ---------------- tf32 mma helpers ------------------------------------------
__device__ __forceinline__ unsigned f2tf32(float x) {
    unsigned y;
    asm("cvt.rna.tf32.f32 %0, %1;" : "=r"(y) : "f"(x));
    return y;
}
__device__ __forceinline__ void mma_tf32(float* c, const unsigned* a, const unsigned* b) {
    asm volatile(
        "mma.sync.aligned.m16n8k8.row.col.f32.tf32.tf32.f32 "
        "{%0,%1,%2,%3},{%4,%5,%6,%7},{%8,%9},{%0,%1,%2,%3};"
        : "+f"(c[0]), "+f"(c[1]), "+f"(c[2]), "+f"(c[3])
        : "r"(a[0]), "r"(a[1]), "r"(a[2]), "r"(a[3]), "r"(b[0]), "r"(b[1]));
}

// ---------------- tf32 GEMM body: C[M,N] (+)= A[M,K] @ B[N,K]^T --------------
// Block tile 64(m) x 128(n), BK=32, 256 threads (8 warps, 2m x 4n, 32x32 each).
// XOR-swizzled smem (conflict-free frag loads, optimal STS.128 wavefronts).
template <bool ATOMIC>
__device__ __forceinline__ void gemm_body(
    const float* __restrict__ A, int lda,
    const float* __restrict__ Bm, int ldb,
    float* __restrict__ C, int ldc,
    int m0, int n0, int k0, int k1)
{
    __shared__ unsigned As[64 * 32];
    __shared__ unsigned Bs[128 * 32];

    const int tid  = threadIdx.x;
    const int lane = tid & 31;
    const int warp = tid >> 5;
    const int wm = warp >> 2;      // 0..1
    const int wn = warp & 3;       // 0..3
    const int fr = lane >> 2;      // 0..7
    const int fc = lane & 3;       // 0..3

    float acc[2][4][4];
#pragma unroll
    for (int mi = 0; mi < 2; mi++)
#pragma unroll
        for (int ni = 0; ni < 4; ni++)
#pragma unroll
            for (int j = 0; j < 4; j++) acc[mi][ni][j] = 0.f;

    for (int kb = k0; kb < k1; kb += 32) {
        float4 av[2], bv[4];
#pragma unroll
        for (int i = 0; i < 2; i++) {
            int idx = tid + i * 256;
            av[i] = *(const float4*)(A + (size_t)(m0 + (idx >> 3)) * lda + kb + (idx & 7) * 4);
        }
#pragma unroll
        for (int i = 0; i < 4; i++) {
            int idx = tid + i * 256;
            bv[i] = *(const float4*)(Bm + (size_t)(n0 + (idx >> 3)) * ldb + kb + (idx & 7) * 4);
        }
        __syncthreads();
#pragma unroll
        for (int i = 0; i < 2; i++) {
            int idx = tid + i * 256;
            int rr = idx >> 3, kq = idx & 7;
            unsigned* dst = &As[rr * 32 + ((kq ^ (rr & 7)) << 2)];
            dst[0] = f2tf32(av[i].x); dst[1] = f2tf32(av[i].y);
            dst[2] = f2tf32(av[i].z); dst[3] = f2tf32(av[i].w);
        }
#pragma unroll
        for (int i = 0; i < 4; i++) {
            int idx = tid + i * 256;
            int rr = idx >> 3, kq = idx & 7;
            unsigned* dst = &Bs[rr * 32 + ((kq ^ (rr & 7)) << 2)];
            dst[0] = f2tf32(bv[i].x); dst[1] = f2tf32(bv[i].y);
            dst[2] = f2tf32(bv[i].z); dst[3] = f2tf32(bv[i].w);
        }
        __syncthreads();

#pragma unroll
        for (int ks = 0; ks < 4; ks++) {
            unsigned afr[2][4], bfr[4][2];
#pragma unroll
            for (int mi = 0; mi < 2; mi++) {
                int r0 = wm * 32 + mi * 16 + fr;     // row of a0/a2
                int r1 = r0 + 8;                      // row of a1/a3
                int g0 = ((ks * 2)     ^ (r0 & 7)) << 2;
                int g1 = ((ks * 2 + 1) ^ (r0 & 7)) << 2;  // (r0&7)==(r1&7)
                afr[mi][0] = As[r0 * 32 + g0 + fc];
                afr[mi][1] = As[r1 * 32 + g0 + fc];
                afr[mi][2] = As[r0 * 32 + g1 + fc];
                afr[mi][3] = As[r1 * 32 + g1 + fc];
            }
#pragma unroll
            for (int ni = 0; ni < 4; ni++) {
                int nr = wn * 32 + ni * 8 + fr;
                int g0 = ((ks * 2)     ^ (nr & 7)) << 2;
                int g1 = ((ks * 2 + 1) ^ (nr & 7)) << 2;
                bfr[ni][0] = Bs[nr * 32 + g0 + fc];
                bfr[ni][1] = Bs[nr * 32 + g1 + fc];
            }
#pragma unroll
            for (int mi = 0; mi < 2; mi++)
#pragma unroll
                for (int ni = 0; ni < 4; ni++)
                    mma_tf32(acc[mi][ni], afr[mi], bfr[ni]);
        }
        __syncthreads();
    }

#pragma unroll
    for (int mi = 0; mi < 2; mi++) {
        int row = m0 + wm * 32 + mi * 16 + fr;
#pragma unroll
        for (int ni = 0; ni < 4; ni++) {
            int col = n0 + wn * 32 + ni * 8 + fc * 2;
            if (ATOMIC) {
                atomicAdd(&C[(size_t)row * ldc + col],       acc[mi][ni][0]);
                atomicAdd(&C[(size_t)row * ldc + col + 1],   acc[mi][ni][1]);
                atomicAdd(&C[(size_t)(row + 8) * ldc + col],     acc[mi][ni][2]);
                atomicAdd(&C[(size_t)(row + 8) * ldc + col + 1], acc[mi][ni][3]);
            } else {
                *(float2*)&C[(size_t)row * ldc + col] =
                    make_float2(acc[mi][ni][0], acc[mi][ni][1]);
                *(float2*)&C[(size_t)(row + 8) * ldc + col] =
                    make_float2(acc[mi][ni][2], acc[mi][ni][3]);
            }
        }
    }
}

// ---------------- GEMM kernel wrappers ---------------------------------------
// Precompute (direct store, full K in-block): grid (N/128, M/64)
__global__ void gemm_pre(const float* __restrict__ A, int lda,
                         const float* __restrict__ Bm, int ldb,
                         float* __restrict__ C, int ldc, int K) {
    gemm_body<false>(A, lda, Bm, ldb, C, ldc,
                     blockIdx.y * 64, blockIdx.x * 128, 0, K);
}

// q = h @ Wq^T : grid (8, 1, 8), split-K kc=128, atomic into g_q (pre-set to bq)
__global__ void gemm_q(const float* __restrict__ Wq) {
    int k0 = blockIdx.z * 128;
    gemm_body<true>(g_h, H, Wq, H, g_q, H, 0, blockIdx.x * 128, k0, k0 + 128);
}

// gates: z<2 -> gh += h @ W_hh^T (K=1024, kc=512)
//        z>=2 -> gi += ctx_t @ W_ih[:,E:]^T (K=2048, kc=512)
// grid (24, 1, 6)
__global__ void gemm_gates(const float* __restrict__ out, int t,
                           const float* __restrict__ W_ih,
                           const float* __restrict__ W_hh) {
    int z = blockIdx.z;
    int n0 = blockIdx.x * 128;
    if (z < 2) {
        int k0 = z * 512;
        gemm_body<true>(g_h, H, W_hh, H, g_gh, G3, 0, n0, k0, k0 + 512);
    } else {
        int k0 = (z - 2) * 512;
        const float* A = out + (size_t)t * OC + (H + E);   // ctx_t rows, stride S*OC
        gemm_body<true>(A, S * OC, W_ih + E, XK, g_gi, G3, 0, n0, k0, k0 + 512);
    }
}

// ---------------- init ------------------------------------------------------
__global__ void k_init(const float* __restrict__ h0, const float* __restrict__ bq) {
    int i = blockIdx.x * 256 + threadIdx.x;
    if (i < B * H) { g_h[i] = h0[i]; g_q[i] = bq[i & (H - 1)]; }
    if (i < B * G3) { g_gi[i] = 0.f; g_gh[i] = 0.f; }
}

// ---------------- embedding gather ------------------------------------------
__global__ void k_emb(const int* __restrict__ tgt,
                      const float* __restrict__ emb,
                      float* __restrict__ out) {
    int row = blockIdx.x;
    int tok = tgt[row];
    const float4* src = (const float4*)(emb + (size_t)tok * E);
    float4* dst = (float4*)(out + (size_t)row * OC + H);
    dst[threadIdx.x] = src[threadIdx.x];
}

// ---------------- attention score (FFMA tanh, bq folded into q) --------------
__global__ void k_score(const float* __restrict__ v) {
    const int l = blockIdx.x, b = blockIdx.y, tid = threadIdx.x;
    const float4* cp = (const float4*)(g_ctxproj + ((size_t)(b * L + l)) * H);
    const float4* q4 = (const float4*)(g_q + b * H);
    const float4* v4 = (const float4*)v;

    float4 c = cp[tid], q = q4[tid], w = v4[tid];
    float s = w.x * tanh_fast(c.x + q.x) + w.y * tanh_fast(c.y + q.y)
            + w.z * tanh_fast(c.z + q.z) + w.w * tanh_fast(c.w + q.w);

#pragma unroll
    for (int o = 16; o; o >>= 1) s += __shfl_xor_sync(0xffffffffu, s, o);
    __shared__ float red[8];
    if ((tid & 31) == 0) red[tid >> 5] = s;
    __syncthreads();
    if (tid == 0) {
        float tot = 0.f;
#pragma unroll
        for (int w8 = 0; w8 < 8; w8++) tot += red[w8];
        g_score[b * L + l] = tot;
    }
}

// ---------------- softmax + ctx_t -> out cols [H+E, OC) ----------------------
__global__ void k_ctx(const float* __restrict__ ctx, float* __restrict__ out, int t) {
    const int b = blockIdx.x;
    const int tid = threadIdx.x;
    __shared__ float attn[L];

    if (tid < L) attn[tid] = g_score[b * L + tid];
    __syncthreads();
    if (tid < 32) {
        float m0 = fmaxf(attn[tid], attn[tid + 32]);
#pragma unroll
        for (int o = 16; o; o >>= 1) m0 = fmaxf(m0, __shfl_xor_sync(0xffffffffu, m0, o));
        float e0 = __expf(attn[tid] - m0);
        float e1 = __expf(attn[tid + 32] - m0);
        float ss = e0 + e1;
#pragma unroll
        for (int o = 16; o; o >>= 1) ss += __shfl_xor_sync(0xffffffffu, ss, o);
        attn[tid] = e0 / ss;
        attn[tid + 32] = e1 / ss;
    }
    __syncthreads();

    const float4* cb4 = (const float4*)(ctx + (size_t)b * L * CDIM);
    float4* orow4 = (float4*)(out + ((size_t)(b * S + t)) * OC + H + E);
    int c4 = blockIdx.y * 256 + tid;        // 0..511
    float4 acc = {0.f, 0.f, 0.f, 0.f};
#pragma unroll 8
    for (int l = 0; l < L; l++) {
        float a = attn[l];
        float4 x = cb4[l * (CDIM / 4) + c4];
        acc.x = fmaf(a, x.x, acc.x); acc.y = fmaf(a, x.y, acc.y);
        acc.z = fmaf(a, x.z, acc.z); acc.w = fmaf(a, x.w, acc.w);
    }
    orow4[c4] = acc;
}

// ---------------- GRU gates + h update + reset scratch -----------------------
__global__ void k_gate(const float* __restrict__ b_ih, const float* __restrict__ b_hh,
                       const float* __restrict__ bq, float* __restrict__ out, int t) {
    const int idx = blockIdx.x * 256 + threadIdx.x;     // b*H + i
    const int b = idx >> 10, i = idx & (H - 1);
    const size_t g  = (size_t)b * G3;
    const size_t ge = ((size_t)(b * S + t)) * G3;

    float ir = g_gi[g + i]         + g_giemb[ge + i]         + b_ih[i];
    float iz = g_gi[g + H + i]     + g_giemb[ge + H + i]     + b_ih[H + i];
    float in_ = g_gi[g + 2*H + i]  + g_giemb[ge + 2*H + i]   + b_ih[2*H + i];
    float hr = g_gh[g + i]         + b_hh[i];
    float hz = g_gh[g + H + i]     + b_hh[H + i];
    float hn = g_gh[g + 2*H + i]   + b_hh[2*H + i];

    float r = 1.f / (1.f + __expf(-(ir + hr)));
    float z = 1.f / (1.f + __expf(-(iz + hz)));
    float n = tanh_fast(in_ + r * hn);
    float hold = g_h[idx];
    float hnew = (1.f - z) * n + z * hold;

    g_h[idx] = hnew;
    out[((size_t)(b * S + t)) * OC + i] = hold;

    g_q[idx] = bq[i];
    g_gi[g + i] = 0.f; g_gi[g + H + i] = 0.f; g_gi[g + 2*H + i] = 0.f;
    g_gh[g + i] = 0.f; g_gh[g + H + i] = 0.f; g_gh[g + 2*H + i] = 0.f;
}

// ---------------- final hidden state -----------------------------------------
__global__ void k_hlast(float* __restrict__ out) {
    int i = blockIdx.x * 256 + threadIdx.x;
    out[(size_t)B * S * OC + i] = g_h[i];
}

// -----------------------------------------------------------------------------
extern "C" void kernel_launch(void* const* d_in, const int* in_sizes, int n_in,
                              void* d_out, int out_size) {
    const int*   tgt  = (const int*)d_in[0];
    const float* ctx  = (const float*)d_in[1];
    const float* h0   = (const float*)d_in[2];
    const float* emb  = (const float*)d_in[3];
    const float* Wc   = (const float*)d_in[4];
    const float* Wq   = (const float*)d_in[5];
    const float* bq   = (const float*)d_in[6];
    const float* v    = (const float*)d_in[7];
    const float* W_ih = (const float*)d_in[8];
    const float* W_hh = (const float*)d_in[9];
    const float* b_ih = (const float*)d_in[10];
    const float* b_hh = (const float*)d_in[11];
    float* out = (float*)d_out;

    float *p_cp, *p_ge;
    cudaGetSymbolAddress((void**)&p_cp, g_ctxproj);
    cudaGetSymbolAddress((void**)&p_ge, g_giemb);

    k_init<<<(B * G3 + 255) / 256, 256>>>(h0, bq);
    k_emb<<<B * S, 128>>>(tgt, emb, out);

    // ctx_proj[B*L, H] = ctx @ Wc^T
    gemm_pre<<<dim3(H / 128, (B * L) / 64), 256>>>(ctx, CDIM, Wc, CDIM, p_cp, H, CDIM);
    // gi_emb[B*S, 3H] = emb_rows @ W_ih[:, :E]^T
    gemm_pre<<<dim3(G3 / 128, (B * S) / 64), 256>>>(out + H, OC, W_ih, XK, p_ge, G3, E);

    for (int t = 0; t < S; t++) {
        gemm_q<<<dim3(H / 128, 1, 8), 256>>>(Wq);
        k_score<<<dim3(L, B), 256>>>(v);
        k_ctx<<<dim3(B, 2), 256>>>(ctx, out, t);
        gemm_gates<<<dim3(G3 / 128, 1, 6), 256>>>(out, t, W_ih, W_hh);
        k_gate<<<(B * H) / 256, 256>>>(b_ih, b_hh, bq, out, t);
    }

    if (out_size >= B * S * OC + B * H)
        k_hlast<<<(B * H) / 256, 256>>>(out);
}